// round 3
// baseline (speedup 1.0000x reference)
#include <cuda_runtime.h>
#include <cstdint>
#include <math.h>

// Problem geometry (fixed by the reference): B=4096, H=W=64, C=8.
#define HW      4096
#define THREADS 256
#define WARPS   8
#define ITERS   16   // HW / THREADS

__global__ __launch_bounds__(THREADS, 2)
void OpponentModelOracle_kernel(const float* __restrict__ x,
                                const float* __restrict__ opp_start,
                                float* __restrict__ out)
{
    const int b = blockIdx.x;
    const float* __restrict__ xb = x + (size_t)b * (HW * 8);

    __shared__ uint32_t s_food[HW / 32];        // 128 words: food bitmap
    __shared__ int s_nf[WARPS], s_no[WARPS], s_fo[WARPS];
    __shared__ int s_k1[WARPS], s_k2[WARPS];
    __shared__ int s_stats[3];                  // n_food, n_opp, first_opp
    __shared__ int s_dec[2];                    // mode, min_idx

    const int t    = threadIdx.x;
    const int lane = t & 31;
    const int w    = t >> 5;

    // ---- Pass A: load x once (float4 covering ch0..3), build bitmaps ----
    float4 v[ITERS];
    #pragma unroll
    for (int it = 0; it < ITERS; ++it) {
        const int cell = (it * WARPS + w) * 32 + lane;     // coalesced, 32B stride
        v[it] = *reinterpret_cast<const float4*>(xb + (size_t)cell * 8);
    }

    int nf = 0, no = 0, fo = 1 << 30;
    #pragma unroll
    for (int it = 0; it < ITERS; ++it) {
        const int word = it * WARPS + w;                   // 0..127
        const unsigned food = __ballot_sync(0xffffffffu, v[it].y == 1.0f);
        const unsigned opp  = __ballot_sync(0xffffffffu, v[it].w == 1.0f);
        if (lane == 0) {
            s_food[word] = food;
            nf += __popc(food);
            no += __popc(opp);
            if (opp) fo = min(fo, word * 32 + (__ffs(opp) - 1));
        }
    }
    if (lane == 0) { s_nf[w] = nf; s_no[w] = no; s_fo[w] = fo; }
    __syncthreads();

    if (t == 0) {
        int NF = 0, NO = 0, FO = 1 << 30;
        #pragma unroll
        for (int i = 0; i < WARPS; ++i) {
            NF += s_nf[i]; NO += s_no[i]; FO = min(FO, s_fo[i]);
        }
        if (FO == (1 << 30)) FO = 0;   // no opponent: value unused downstream
        s_stats[0] = NF; s_stats[1] = NO; s_stats[2] = FO;
    }
    __syncthreads();

    const int first = s_stats[2];
    const int orow = first >> 6;
    const int ocol = first & 63;

    // ---- Pass B: top-2 (d2, idx) keys over food cells (from smem bitmap) ----
    // key = (d2 << 12) | cell ; lexicographic min == argmin with first-index
    // tie-break (sqrt is strictly monotone & injective on these integers).
    int k1 = 0x7fffffff, k2 = 0x7fffffff;
    #pragma unroll
    for (int it = 0; it < ITERS; ++it) {
        const int cell = it * THREADS + t;
        if ((s_food[cell >> 5] >> (cell & 31)) & 1u) {
            const int dr = (cell >> 6) - orow;
            const int dc = (cell & 63) - ocol;
            const int key = ((dr * dr + dc * dc) << 12) | cell;
            if (key < k1) { k2 = k1; k1 = key; }
            else if (key < k2) { k2 = key; }
        }
    }
    // warp top-2 merge
    #pragma unroll
    for (int off = 16; off; off >>= 1) {
        const int o1 = __shfl_down_sync(0xffffffffu, k1, off);
        const int o2 = __shfl_down_sync(0xffffffffu, k2, off);
        const int n1 = min(k1, o1);
        const int n2 = min(max(k1, o1), min(k2, o2));
        k1 = n1; k2 = n2;
    }
    if (lane == 0) { s_k1[w] = k1; s_k2[w] = k2; }
    __syncthreads();

    if (t == 0) {
        int K1 = s_k1[0], K2 = s_k2[0];
        #pragma unroll
        for (int i = 1; i < WARPS; ++i) {
            const int o1 = s_k1[i], o2 = s_k2[i];
            const int n1 = min(K1, o1);
            const int n2 = min(max(K1, o1), min(K2, o2));
            K1 = n1; K2 = n2;
        }
        const int NF = s_stats[0], NO = s_stats[1];
        const int min_idx = K1 & 4095;
        const float min1 = sqrtf((float)(K1 >> 12));
        const float min2 = sqrtf((float)(K2 >> 12));   // sentinel only if NF<=1 (unused then)
        const float diff = min2 - min1;

        const float os0 = opp_start[0], os1 = opp_start[1];
        const bool matches   = ((float)orow == os0) && ((float)ocol == os1);
        const bool branchA   = (NF > 1) && (NO > 0) && !matches;
        const bool ambiguous = (branchA && diff < 0.1f) || ((NF > 1) && !branchA);
        const bool nearest   = (branchA && diff >= 0.1f) || (NF == 1);

        s_dec[0] = ambiguous ? 1 : (nearest ? 2 : 0);
        s_dec[1] = min_idx;
    }
    __syncthreads();

    // ---- Pass C: write output ----
    const int mode    = s_dec[0];
    const int min_idx = s_dec[1];
    float* __restrict__ ob = out + (size_t)b * HW;
    #pragma unroll
    for (int it = 0; it < ITERS; ++it) {
        const int cell = it * THREADS + t;
        bool h;
        if (mode == 1)      h = (s_food[cell >> 5] >> (cell & 31)) & 1u;
        else                h = (mode == 2) && (cell == min_idx);
        ob[cell] = h ? 10.0f : -10.0f;
    }
}

extern "C" void kernel_launch(void* const* d_in, const int* in_sizes, int n_in,
                              void* d_out, int out_size)
{
    const float* x   = (const float*)d_in[0];   // [B,64,64,8] fp32
    const float* os  = (const float*)d_in[1];   // [2] fp32
    float* out = (float*)d_out;                 // [B,64,64] fp32
    const int B = in_sizes[0] / (HW * 8);
    OpponentModelOracle_kernel<<<B, THREADS>>>(x, os, out);
}

// round 4
// speedup vs baseline: 1.0003x; 1.0003x over previous
#include <cuda_runtime.h>
#include <cstdint>
#include <math.h>

// Problem geometry (fixed by the reference): B=4096, H=W=64, C=8.
#define HW      4096
#define THREADS 256
#define WARPS   8
#define ITERS   16   // HW / THREADS
#define CHUNK   8    // float4 staging per half-pass (keeps regs ~48 -> 5 CTAs/SM)

__global__ __launch_bounds__(THREADS, 5)
void OpponentModelOracle_kernel(const float* __restrict__ x,
                                const float* __restrict__ opp_start,
                                float* __restrict__ out)
{
    const int b = blockIdx.x;
    const float* __restrict__ xb = x + (size_t)b * (HW * 8);

    __shared__ uint32_t s_food[HW / 32];        // 128 words: food bitmap
    __shared__ int s_nf[WARPS], s_no[WARPS], s_fo[WARPS];
    __shared__ int s_k1[WARPS], s_k2[WARPS];
    __shared__ int s_stats[3];                  // n_food, n_opp, first_opp
    __shared__ int s_dec[2];                    // mode, min_idx

    const int t    = threadIdx.x;
    const int lane = t & 31;
    const int w    = t >> 5;

    // ---- Pass A: stream x once (float4 covers ch0..3), build bitmaps ----
    // Two chunks of 8 outstanding LDG.128 each: MLP=8/thread, half the
    // register staging of a single 16-deep batch.
    int nf = 0, no = 0, fo = 1 << 30;
    #pragma unroll
    for (int c = 0; c < ITERS / CHUNK; ++c) {
        float4 v[CHUNK];
        #pragma unroll
        for (int i = 0; i < CHUNK; ++i) {
            const int it   = c * CHUNK + i;
            const int cell = (it * WARPS + w) * 32 + lane;   // coalesced, 32B stride
            v[i] = __ldcs(reinterpret_cast<const float4*>(xb + (size_t)cell * 8));
        }
        #pragma unroll
        for (int i = 0; i < CHUNK; ++i) {
            const int word = (c * CHUNK + i) * WARPS + w;    // 0..127
            const unsigned food = __ballot_sync(0xffffffffu, v[i].y == 1.0f);
            const unsigned opp  = __ballot_sync(0xffffffffu, v[i].w == 1.0f);
            if (lane == 0) {
                s_food[word] = food;
                nf += __popc(food);
                no += __popc(opp);
                if (opp) fo = min(fo, word * 32 + (__ffs(opp) - 1));
            }
        }
    }
    if (lane == 0) { s_nf[w] = nf; s_no[w] = no; s_fo[w] = fo; }
    __syncthreads();

    if (t == 0) {
        int NF = 0, NO = 0, FO = 1 << 30;
        #pragma unroll
        for (int i = 0; i < WARPS; ++i) {
            NF += s_nf[i]; NO += s_no[i]; FO = min(FO, s_fo[i]);
        }
        if (FO == (1 << 30)) FO = 0;   // no opponent: value unused downstream
        s_stats[0] = NF; s_stats[1] = NO; s_stats[2] = FO;
    }
    __syncthreads();

    const int first = s_stats[2];
    const int orow = first >> 6;
    const int ocol = first & 63;

    // ---- Pass B: top-2 (d2, idx) keys over food cells (smem bitmap only) ----
    // key = (d2 << 12) | cell ; lexicographic min == argmin with first-index
    // tie-break (sqrt is strictly monotone & injective on these integers).
    int k1 = 0x7fffffff, k2 = 0x7fffffff;
    #pragma unroll
    for (int it = 0; it < ITERS; ++it) {
        const int cell = it * THREADS + t;
        if ((s_food[cell >> 5] >> (cell & 31)) & 1u) {
            const int dr = (cell >> 6) - orow;
            const int dc = (cell & 63) - ocol;
            const int key = ((dr * dr + dc * dc) << 12) | cell;
            if (key < k1) { k2 = k1; k1 = key; }
            else if (key < k2) { k2 = key; }
        }
    }
    // warp top-2 merge
    #pragma unroll
    for (int off = 16; off; off >>= 1) {
        const int o1 = __shfl_down_sync(0xffffffffu, k1, off);
        const int o2 = __shfl_down_sync(0xffffffffu, k2, off);
        const int n1 = min(k1, o1);
        const int n2 = min(max(k1, o1), min(k2, o2));
        k1 = n1; k2 = n2;
    }
    if (lane == 0) { s_k1[w] = k1; s_k2[w] = k2; }
    __syncthreads();

    if (t == 0) {
        int K1 = s_k1[0], K2 = s_k2[0];
        #pragma unroll
        for (int i = 1; i < WARPS; ++i) {
            const int o1 = s_k1[i], o2 = s_k2[i];
            const int n1 = min(K1, o1);
            const int n2 = min(max(K1, o1), min(K2, o2));
            K1 = n1; K2 = n2;
        }
        const int NF = s_stats[0], NO = s_stats[1];
        const int min_idx = K1 & 4095;
        const float min1 = sqrtf((float)(K1 >> 12));
        const float min2 = sqrtf((float)(K2 >> 12));   // sentinel only if NF<=1 (unused then)
        const float diff = min2 - min1;

        const float os0 = opp_start[0], os1 = opp_start[1];
        const bool matches   = ((float)orow == os0) && ((float)ocol == os1);
        const bool branchA   = (NF > 1) && (NO > 0) && !matches;
        const bool ambiguous = (branchA && diff < 0.1f) || ((NF > 1) && !branchA);
        const bool nearest   = (branchA && diff >= 0.1f) || (NF == 1);

        s_dec[0] = ambiguous ? 1 : (nearest ? 2 : 0);
        s_dec[1] = min_idx;
    }
    __syncthreads();

    // ---- Pass C: write output as float4 (4x STG.128 per thread) ----
    const int mode    = s_dec[0];
    const int min_idx = s_dec[1];
    float4* __restrict__ ob4 = reinterpret_cast<float4*>(out + (size_t)b * HW);
    #pragma unroll
    for (int j = 0; j < 4; ++j) {
        const int q    = j * THREADS + t;   // float4 index, 0..1023
        const int cell = q * 4;             // base cell (word-aligned group of 4)
        unsigned bits;
        if (mode == 1)      bits = (s_food[cell >> 5] >> (cell & 31)) & 0xFu;
        else if (mode == 2) bits = (min_idx >> 2 == q) ? (1u << (min_idx & 3)) : 0u;
        else                bits = 0u;
        float4 o;
        o.x = (bits & 1u) ? 10.0f : -10.0f;
        o.y = (bits & 2u) ? 10.0f : -10.0f;
        o.z = (bits & 4u) ? 10.0f : -10.0f;
        o.w = (bits & 8u) ? 10.0f : -10.0f;
        __stcs(&ob4[q], o);
    }
}

extern "C" void kernel_launch(void* const* d_in, const int* in_sizes, int n_in,
                              void* d_out, int out_size)
{
    const float* x   = (const float*)d_in[0];   // [B,64,64,8] fp32
    const float* os  = (const float*)d_in[1];   // [2] fp32
    float* out = (float*)d_out;                 // [B,64,64] fp32
    const int B = in_sizes[0] / (HW * 8);
    OpponentModelOracle_kernel<<<B, THREADS>>>(x, os, out);
}